// round 4
// baseline (speedup 1.0000x reference)
#include <cuda_runtime.h>
#include <math.h>
#include <stdint.h>

#define BATCH 2
#define SEQ   2048
#define NH    12
#define HD    64
#define EMB   768     // NH*HD
#define PLMD  1280
#define SD    128
#define FFD   640
#define ROWS  (BATCH*SEQ)                 // 4096
#define OUT_ELEMS ((long)ROWS*PLMD)       // 5,242,880
#define LOG2_10000 13.287712379549449f

// ---------------- scratch (static __device__, no allocation) ----------------
__device__ __align__(16) float g_qp[ROWS*EMB];
__device__ __align__(16) float g_kp[ROWS*EMB];
__device__ __align__(16) float g_vp[ROWS*EMB];
__device__ __align__(16) float g_vt[ROWS*EMB];   // [B,H,D,S]
__device__ __align__(16) float g_vals[ROWS*EMB]; // [B,S,E]
__device__ __align__(16) float g_x[ROWS*PLMD];
__device__ __align__(16) float g_ln[ROWS*PLMD];
__device__ __align__(16) float g_ff[ROWS*FFD];
__device__ __align__(16) float g_cos[SEQ*32];
__device__ __align__(16) float g_sin[SEQ*32];

// ---------------- helpers ----------------
__device__ __forceinline__ uint32_t f2tf32(uint32_t xbits) {
    uint32_t u;
    float f = __uint_as_float(xbits);
    asm("cvt.rna.tf32.f32 %0, %1;" : "=r"(u) : "f"(f));
    return u;
}
__device__ __forceinline__ uint32_t f2tf32f(float f) {
    uint32_t u;
    asm("cvt.rna.tf32.f32 %0, %1;" : "=r"(u) : "f"(f));
    return u;
}

__device__ __forceinline__ void mma_tf32(float* c, const uint32_t* a, const uint32_t* b) {
    asm volatile("mma.sync.aligned.m16n8k8.row.col.f32.tf32.tf32.f32 "
        "{%0,%1,%2,%3}, {%4,%5,%6,%7}, {%8,%9}, {%0,%1,%2,%3};"
        : "+f"(c[0]), "+f"(c[1]), "+f"(c[2]), "+f"(c[3])
        : "r"(a[0]), "r"(a[1]), "r"(a[2]), "r"(a[3]), "r"(b[0]), "r"(b[1]));
}

__device__ __forceinline__ void cp_async16(uint32_t smem_dst, const void* gsrc) {
    asm volatile("cp.async.cg.shared.global [%0], [%1], 16;" :: "r"(smem_dst), "l"(gsrc));
}
__device__ __forceinline__ void cp_commit() { asm volatile("cp.async.commit_group;"); }
__device__ __forceinline__ void cp_wait1()  { asm volatile("cp.async.wait_group 1;"); }
__device__ __forceinline__ void cp_wait0()  { asm volatile("cp.async.wait_group 0;"); }

// ---------------- RoPE cos/sin tables ----------------
__global__ void rope_table_kernel() {
    int idx = blockIdx.x * blockDim.x + threadIdx.x;
    if (idx >= SEQ*32) return;
    int s = idx >> 5, j = idx & 31;
    float inv = exp2f(-(float)j * (LOG2_10000 / 32.0f));
    float freq = (float)s * inv;
    float sn, c;
    sincosf(freq, &sn, &c);
    g_cos[idx] = c; g_sin[idx] = sn;
}

// ---------------- TF32 pipelined GEMM: C = alpha*A@B^T (+bias)(+extra)(gelu) ----
// EPI: 0 = (+bias), 1 = +bias+extra, 2 = gelu(+bias)
template<int EPI, int BM, int BN, int WARPS_M, int WARPS_N>
__global__ __launch_bounds__(256)
void gemm_tf32(const float* __restrict__ A, const float* __restrict__ B,
               const float* __restrict__ bias, const float* __restrict__ extra,
               float* __restrict__ C,
               int K, int sAm, int sBn, int ldc,
               long zA, long zB, long zC, float alpha)
{
    constexpr int BK   = 32;
    constexpr int LDSW = 36;
    constexpr int WM = BM / WARPS_M, WN = BN / WARPS_N;
    constexpr int MF = WM / 16, NF = WN / 8;
    constexpr int ASTG = BM * LDSW;
    constexpr int BSTG = BN * LDSW;

    extern __shared__ uint32_t smem[];
    uint32_t* As = smem;
    uint32_t* Bs = smem + 2 * ASTG;

    const int tid  = threadIdx.x;
    const int lane = tid & 31;
    const int warp = tid >> 5;
    const int wm = warp % WARPS_M, wn = warp / WARPS_M;
    const int row0 = blockIdx.y * BM, col0 = blockIdx.x * BN;
    A += (long)blockIdx.z * zA + (long)row0 * sAm;
    B += (long)blockIdx.z * zB + (long)col0 * sBn;
    C += (long)blockIdx.z * zC;

    const uint32_t smem_base = (uint32_t)__cvta_generic_to_shared(smem);

    const int r  = lane >> 2;
    const int cq = lane & 3;

    float acc[MF][NF][4];
#pragma unroll
    for (int m = 0; m < MF; m++)
#pragma unroll
        for (int n = 0; n < NF; n++)
#pragma unroll
            for (int j = 0; j < 4; j++) acc[m][n][j] = 0.f;

    const int lrow = tid >> 3;
    const int lf   = (tid & 7) * 4;

    auto prefetch = [&](int stage, int k0) {
#pragma unroll
        for (int i = 0; i < BM/32; i++) {
            int row = lrow + i*32;
            cp_async16(smem_base + (stage*ASTG + row*LDSW + lf)*4,
                       A + (long)row*sAm + k0 + lf);
        }
#pragma unroll
        for (int i = 0; i < BN/32; i++) {
            int row = lrow + i*32;
            cp_async16(smem_base + ((2*ASTG) + stage*BSTG + row*LDSW + lf)*4,
                       B + (long)row*sBn + k0 + lf);
        }
    };

    const int nk = K / BK;
    prefetch(0, 0);
    cp_commit();

    for (int kt = 0; kt < nk; kt++) {
        const int stage = kt & 1;
        if (kt + 1 < nk) prefetch(stage ^ 1, (kt+1) * BK);
        cp_commit();
        cp_wait1();
        __syncthreads();

        const uint32_t* Ast = As + stage * ASTG;
        const uint32_t* Bst = Bs + stage * BSTG;
#pragma unroll
        for (int ks = 0; ks < BK/8; ks++) {
            const int kk = ks * 8;
            uint32_t af[MF][4], bf[NF][2];
#pragma unroll
            for (int m = 0; m < MF; m++) {
                int base = (wm*WM + m*16 + r)*LDSW + kk + cq;
                af[m][0] = f2tf32(Ast[base]);
                af[m][1] = f2tf32(Ast[base + 8*LDSW]);
                af[m][2] = f2tf32(Ast[base + 4]);
                af[m][3] = f2tf32(Ast[base + 8*LDSW + 4]);
            }
#pragma unroll
            for (int n = 0; n < NF; n++) {
                int base = (wn*WN + n*8 + r)*LDSW + kk + cq;
                bf[n][0] = f2tf32(Bst[base]);
                bf[n][1] = f2tf32(Bst[base + 4]);
            }
#pragma unroll
            for (int m = 0; m < MF; m++)
#pragma unroll
                for (int n = 0; n < NF; n++)
                    mma_tf32(acc[m][n], af[m], bf[n]);
        }
        __syncthreads();
    }

#pragma unroll
    for (int m = 0; m < MF; m++) {
#pragma unroll
        for (int n = 0; n < NF; n++) {
            int row = row0 + wm*WM + m*16 + r;
            int col = col0 + wn*WN + n*8 + 2*cq;
            float v0 = alpha * acc[m][n][0];
            float v1 = alpha * acc[m][n][1];
            float v2 = alpha * acc[m][n][2];
            float v3 = alpha * acc[m][n][3];
            if (bias) { v0 += bias[col]; v1 += bias[col+1]; v2 += bias[col]; v3 += bias[col+1]; }
            if (EPI == 1) {
                v0 += extra[(long)row*ldc + col];
                v1 += extra[(long)row*ldc + col + 1];
                v2 += extra[(long)(row+8)*ldc + col];
                v3 += extra[(long)(row+8)*ldc + col + 1];
            }
            if (EPI == 2) {
                v0 = 0.5f * v0 * (1.f + erff(v0 * 0.70710678118654752f));
                v1 = 0.5f * v1 * (1.f + erff(v1 * 0.70710678118654752f));
                v2 = 0.5f * v2 * (1.f + erff(v2 * 0.70710678118654752f));
                v3 = 0.5f * v3 * (1.f + erff(v3 * 0.70710678118654752f));
            }
            *reinterpret_cast<float2*>(&C[(long)row*ldc + col])     = make_float2(v0, v1);
            *reinterpret_cast<float2*>(&C[(long)(row+8)*ldc + col]) = make_float2(v2, v3);
        }
    }
}

// ---------------- QK^T with fused RoPE ----------------
// Reads q/k projections in [B,S,H*D] layout, applies RoPE during staging,
// computes logits*0.125 into attn [BH, S, S]. K dim = 64, single slab.
__global__ __launch_bounds__(256)
void qk_rope_kernel(const float* __restrict__ qp, const float* __restrict__ kp,
                    float* __restrict__ attn)
{
    constexpr int LDSW = 68;
    __shared__ float Qs[128*LDSW];
    __shared__ float Ks[128*LDSW];

    const int tid  = threadIdx.x;
    const int lane = tid & 31;
    const int warp = tid >> 5;
    const int wm = warp & 1, wn = warp >> 1;   // 2 x 4 warps
    const int bh = blockIdx.z;
    const int b = bh / NH, h = bh % NH;
    const int row0 = blockIdx.y * 128, col0 = blockIdx.x * 128;

    const float* qb = qp + (long)b*SEQ*EMB + h*HD;
    const float* kb = kp + (long)b*SEQ*EMB + h*HD;

    // stage with RoPE: idx -> r = idx>>4 (tile row), f = idx&15 (float4 within 64)
#pragma unroll
    for (int i = 0; i < 8; i++) {
        int idx = tid + i*256;
        int r = idx >> 4, f = idx & 15;
        int d0 = f*4;
        int j0 = d0 & 31;
        float sgn = (d0 < 32) ? -1.f : 1.f;
        {   // Q
            int s = row0 + r;
            float4 x  = *reinterpret_cast<const float4*>(qb + (long)s*EMB + d0);
            float4 p  = *reinterpret_cast<const float4*>(qb + (long)s*EMB + (d0 ^ 32));
            float4 c  = *reinterpret_cast<const float4*>(&g_cos[s*32 + j0]);
            float4 sn = *reinterpret_cast<const float4*>(&g_sin[s*32 + j0]);
            float4 o;
            o.x = x.x*c.x + sgn*p.x*sn.x;
            o.y = x.y*c.y + sgn*p.y*sn.y;
            o.z = x.z*c.z + sgn*p.z*sn.z;
            o.w = x.w*c.w + sgn*p.w*sn.w;
            *reinterpret_cast<float4*>(&Qs[r*LDSW + d0]) = o;
        }
        {   // K
            int s = col0 + r;
            float4 x  = *reinterpret_cast<const float4*>(kb + (long)s*EMB + d0);
            float4 p  = *reinterpret_cast<const float4*>(kb + (long)s*EMB + (d0 ^ 32));
            float4 c  = *reinterpret_cast<const float4*>(&g_cos[s*32 + j0]);
            float4 sn = *reinterpret_cast<const float4*>(&g_sin[s*32 + j0]);
            float4 o;
            o.x = x.x*c.x + sgn*p.x*sn.x;
            o.y = x.y*c.y + sgn*p.y*sn.y;
            o.z = x.z*c.z + sgn*p.z*sn.z;
            o.w = x.w*c.w + sgn*p.w*sn.w;
            *reinterpret_cast<float4*>(&Ks[r*LDSW + d0]) = o;
        }
    }
    __syncthreads();

    const int r  = lane >> 2;
    const int cq = lane & 3;
    float acc[4][4][4];
#pragma unroll
    for (int m = 0; m < 4; m++)
#pragma unroll
        for (int n = 0; n < 4; n++)
#pragma unroll
            for (int j = 0; j < 4; j++) acc[m][n][j] = 0.f;

#pragma unroll
    for (int ks = 0; ks < 8; ks++) {
        const int kk = ks * 8;
        uint32_t af[4][4], bf[4][2];
#pragma unroll
        for (int m = 0; m < 4; m++) {
            int base = (wm*64 + m*16 + r)*LDSW + kk + cq;
            af[m][0] = f2tf32f(Qs[base]);
            af[m][1] = f2tf32f(Qs[base + 8*LDSW]);
            af[m][2] = f2tf32f(Qs[base + 4]);
            af[m][3] = f2tf32f(Qs[base + 8*LDSW + 4]);
        }
#pragma unroll
        for (int n = 0; n < 4; n++) {
            int base = (wn*32 + n*8 + r)*LDSW + kk + cq;
            bf[n][0] = f2tf32f(Ks[base]);
            bf[n][1] = f2tf32f(Ks[base + 4]);
        }
#pragma unroll
        for (int m = 0; m < 4; m++)
#pragma unroll
            for (int n = 0; n < 4; n++)
                mma_tf32(acc[m][n], af[m], bf[n]);
    }

    float* Cb = attn + (long)bh*SEQ*SEQ;
#pragma unroll
    for (int m = 0; m < 4; m++) {
#pragma unroll
        for (int n = 0; n < 4; n++) {
            int row = row0 + wm*64 + m*16 + r;
            int col = col0 + wn*32 + n*8 + 2*cq;
            *reinterpret_cast<float2*>(&Cb[(long)row*SEQ + col]) =
                make_float2(0.125f*acc[m][n][0], 0.125f*acc[m][n][1]);
            *reinterpret_cast<float2*>(&Cb[(long)(row+8)*SEQ + col]) =
                make_float2(0.125f*acc[m][n][2], 0.125f*acc[m][n][3]);
        }
    }
}

// ---------------- fused softmax + AV + head-merge ----------------
// grid (SEQ/16, B*NH), 256 threads. Block owns 16 full logit rows (SMEM),
// computes softmax stats, then streams: writes normalized probs to attn
// and accumulates O = P@V (tf32 mma) into vals [B,S,H*D].
#define FS_LP 2052          // padded row stride (words) for P
#define FS_LV 68            // padded row stride for V chunk
__global__ __launch_bounds__(256)
void fsav_kernel(float* __restrict__ attn, const float* __restrict__ vt,
                 float* __restrict__ vals)
{
    extern __shared__ float sm[];
    float* P  = sm;                       // [16][FS_LP]
    float* Vs = sm + 16*FS_LP;            // [2][64*FS_LV]
    __shared__ float inv_s[16];

    const int tid  = threadIdx.x;
    const int lane = tid & 31;
    const int warp = tid >> 5;
    const int bh = blockIdx.y;
    const int b = bh / NH, h = bh % NH;
    const int row0 = blockIdx.x * 16;

    float* arow = attn + (long)bh*SEQ*SEQ + (long)row0*SEQ;
    const float* vb = vt + (long)bh*HD*SEQ;

    const uint32_t smem_base = (uint32_t)__cvta_generic_to_shared(sm);
    const uint32_t vs_base   = smem_base + 16*FS_LP*4;

    // ---- phase 1: load 16 x 2048 logits ----
#pragma unroll
    for (int i = 0; i < 32; i++) {
        int idx = tid + i*256;            // 0..8191 float4s
        int r = idx >> 9, f = idx & 511;
        cp_async16(smem_base + (r*FS_LP + f*4)*4, arow + (long)r*SEQ + f*4);
    }
    cp_commit();

    // prefetch V chunk 0 while waiting: 64 d x 64 s
    auto stage_v = [&](int stg, int kc) {
#pragma unroll
        for (int i = 0; i < 4; i++) {
            int idx = tid + i*256;        // 0..1023 float4s
            int d = idx >> 4, f = (idx & 15)*4;
            cp_async16(vs_base + (stg*64*FS_LV + d*FS_LV + f)*4,
                       vb + (long)d*SEQ + kc*64 + f);
        }
    };
    stage_v(0, 0);
    cp_commit();
    cp_wait1();          // P loaded (V chunk 0 may still be in flight)
    __syncthreads();

    // ---- phase 2: row stats; store unnormalized exp back to smem ----
    {
#pragma unroll
        for (int rr = 0; rr < 2; rr++) {
            int row = warp*2 + rr;
            float* pr = P + row*FS_LP;
            float m = -1e30f;
#pragma unroll
            for (int j = 0; j < 16; j++) {
                float4 v = *reinterpret_cast<float4*>(&pr[(lane + j*32)*4]);
                m = fmaxf(fmaxf(fmaxf(m, v.x), fmaxf(v.y, v.z)), v.w);
            }
#pragma unroll
            for (int o = 16; o > 0; o >>= 1) m = fmaxf(m, __shfl_xor_sync(0xffffffffu, m, o));
            float sum = 0.f;
#pragma unroll
            for (int j = 0; j < 16; j++) {
                float4 v = *reinterpret_cast<float4*>(&pr[(lane + j*32)*4]);
                v.x = expf(v.x - m); v.y = expf(v.y - m);
                v.z = expf(v.z - m); v.w = expf(v.w - m);
                sum += v.x + v.y + v.z + v.w;
                *reinterpret_cast<float4*>(&pr[(lane + j*32)*4]) = v;
            }
#pragma unroll
            for (int o = 16; o > 0; o >>= 1) sum += __shfl_xor_sync(0xffffffffu, sum, o);
            if (lane == 0) inv_s[row] = 1.f / sum;
        }
    }
    __syncthreads();

    // ---- phase 3: stream probs out + accumulate AV ----
    const int r  = lane >> 2;
    const int cq = lane & 3;
    float acc[4] = {0.f, 0.f, 0.f, 0.f};
    const int prow = tid >> 4;             // probs-store row (0..15)
    const int pcol = (tid & 15) * 4;       // base col within 64-chunk
    const float pinv = inv_s[prow];

    for (int kc = 0; kc < 32; kc++) {
        const int stg = kc & 1;
        if (kc + 1 < 32) stage_v(stg ^ 1, kc + 1);
        cp_commit();
        cp_wait1();
        __syncthreads();

        // store normalized probs for this 64-col chunk (1 float4/thread)
        {
            float4 v = *reinterpret_cast<float4*>(&P[prow*FS_LP + kc*64 + pcol]);
            v.x *= pinv; v.y *= pinv; v.z *= pinv; v.w *= pinv;
            float4* dst = reinterpret_cast<float4*>(arow + (long)prow*SEQ + kc*64 + pcol);
            __stcs(dst, v);
        }

        // mma: 8 k-steps of m16n8k8; warp covers cols warp*8..warp*8+7
        const float* Vc = Vs + stg*64*FS_LV;
#pragma unroll
        for (int ks = 0; ks < 8; ks++) {
            const int kk = kc*64 + ks*8;
            uint32_t a[4], bfr[2];
            a[0] = f2tf32f(P[r*FS_LP + kk + cq]);
            a[1] = f2tf32f(P[(r+8)*FS_LP + kk + cq]);
            a[2] = f2tf32f(P[r*FS_LP + kk + cq + 4]);
            a[3] = f2tf32f(P[(r+8)*FS_LP + kk + cq + 4]);
            bfr[0] = f2tf32f(Vc[(warp*8 + r)*FS_LV + ks*8 + cq]);
            bfr[1] = f2tf32f(Vc[(warp*8 + r)*FS_LV + ks*8 + cq + 4]);
            mma_tf32(acc, a, bfr);
        }
        __syncthreads();
    }

    // ---- write O, scaled by inv, directly in [B,S,H*D] layout ----
    {
        int s0 = row0 + r, s1 = row0 + r + 8;
        float i0 = inv_s[r], i1 = inv_s[r + 8];
        int col = h*HD + warp*8 + 2*cq;
        *reinterpret_cast<float2*>(&vals[(long)(b*SEQ + s0)*EMB + col]) =
            make_float2(acc[0]*i0, acc[1]*i0);
        *reinterpret_cast<float2*>(&vals[(long)(b*SEQ + s1)*EMB + col]) =
            make_float2(acc[2]*i1, acc[3]*i1);
    }
}

// ---------------- V transpose: [B,S,H*D] -> [B,H,D,S] ----------------
__global__ void v_transpose_kernel(const float* __restrict__ src, float* __restrict__ dst)
{
    int idx = blockIdx.x * blockDim.x + threadIdx.x;
    if (idx >= ROWS*EMB) return;
    int d = idx & 63;
    int s = (idx >> 6) & (SEQ-1);
    int t = idx >> 17;
    int h = t % NH;
    int b = t / NH;
    float val = src[(long)(b*SEQ + s)*EMB + h*HD + d];
    dst[((long)(b*NH + h)*HD + d)*SEQ + s] = val;
}

// ---------------- LayerNorm over 1280 ----------------
__global__ __launch_bounds__(256) void layernorm_kernel(const float* __restrict__ x,
    const float* __restrict__ g, const float* __restrict__ b, float* __restrict__ y)
{
    __shared__ float buf[PLMD];
    __shared__ float red[256];
    long row = blockIdx.x;
    const float* xr = x + row*PLMD;
    int tid = threadIdx.x;
    float s = 0.f;
    for (int i = tid; i < PLMD; i += 256) { float t = xr[i]; buf[i] = t; s += t; }
    red[tid] = s; __syncthreads();
    for (int st = 128; st > 0; st >>= 1) { if (tid < st) red[tid] += red[tid+st]; __syncthreads(); }
    float mu = red[0] * (1.f/PLMD); __syncthreads();
    float vs = 0.f;
    for (int i = tid; i < PLMD; i += 256) { float d = buf[i] - mu; vs += d*d; }
    red[tid] = vs; __syncthreads();
    for (int st = 128; st > 0; st >>= 1) { if (tid < st) red[tid] += red[tid+st]; __syncthreads(); }
    float rstd = rsqrtf(red[0] * (1.f/PLMD) + 1e-5f);
    float* yr = y + row*PLMD;
    for (int i = tid; i < PLMD; i += 256) yr[i] = (buf[i] - mu) * rstd * g[i] + b[i];
}

// ---------------- launch ----------------
extern "C" void kernel_launch(void* const* d_in, const int* in_sizes, int n_in,
                              void* d_out, int out_size)
{
    const float* s_repre = (const float*)d_in[0];
    const float* plm     = (const float*)d_in[1];
    const float* Wq = (const float*)d_in[2];  const float* bq = (const float*)d_in[3];
    const float* Wk = (const float*)d_in[4];  const float* bk = (const float*)d_in[5];
    const float* Wv = (const float*)d_in[6];  const float* bv = (const float*)d_in[7];
    const float* Wo = (const float*)d_in[8];  const float* bo = (const float*)d_in[9];
    const float* lng = (const float*)d_in[10]; const float* lnb = (const float*)d_in[11];
    const float* Wd = (const float*)d_in[12]; const float* bd = (const float*)d_in[13];
    const float* Wu = (const float*)d_in[14]; const float* bu = (const float*)d_in[15];

    float* out  = (float*)d_out;
    float* attn = out + OUT_ELEMS;   // tuple order: (out, attention)

    float *qp,*kp,*vp,*vt,*vals,*x,*ln,*ff;
    cudaGetSymbolAddress((void**)&qp, g_qp);
    cudaGetSymbolAddress((void**)&kp, g_kp);
    cudaGetSymbolAddress((void**)&vp, g_vp);
    cudaGetSymbolAddress((void**)&vt, g_vt);
    cudaGetSymbolAddress((void**)&vals, g_vals);
    cudaGetSymbolAddress((void**)&x, g_x);
    cudaGetSymbolAddress((void**)&ln, g_ln);
    cudaGetSymbolAddress((void**)&ff, g_ff);

    const int S_128_128 = 2 * (128 + 128) * 36 * 4;   // 73728
    const int S_FSAV = (16*FS_LP + 2*64*FS_LV) * 4;   // 166144
    cudaFuncSetAttribute(gemm_tf32<0,128,128,2,4>, cudaFuncAttributeMaxDynamicSharedMemorySize, S_128_128);
    cudaFuncSetAttribute(gemm_tf32<1,128,128,2,4>, cudaFuncAttributeMaxDynamicSharedMemorySize, S_128_128);
    cudaFuncSetAttribute(gemm_tf32<2,128,128,2,4>, cudaFuncAttributeMaxDynamicSharedMemorySize, S_128_128);
    cudaFuncSetAttribute(fsav_kernel, cudaFuncAttributeMaxDynamicSharedMemorySize, S_FSAV);

    const int tot = ROWS*EMB;

    // RoPE tables
    rope_table_kernel<<<(SEQ*32 + 255)/256, 256>>>();

    // QKV projections
    gemm_tf32<0,128,128,2,4><<<dim3(EMB/128, ROWS/128, 1), 256, S_128_128>>>(
        plm, Wq, bq, nullptr, qp, PLMD, PLMD, PLMD, EMB, 0,0,0, 1.f);
    gemm_tf32<0,128,128,2,4><<<dim3(EMB/128, ROWS/128, 1), 256, S_128_128>>>(
        s_repre, Wk, bk, nullptr, kp, SD, SD, SD, EMB, 0,0,0, 1.f);
    gemm_tf32<0,128,128,2,4><<<dim3(EMB/128, ROWS/128, 1), 256, S_128_128>>>(
        s_repre, Wv, bv, nullptr, vp, SD, SD, SD, EMB, 0,0,0, 1.f);

    // V transpose to [B,H,D,S]
    v_transpose_kernel<<<(tot+255)/256, 256>>>(vp, vt);

    // logits = RoPE(q) @ RoPE(k)^T / 8 -> attn region of d_out
    qk_rope_kernel<<<dim3(SEQ/128, SEQ/128, BATCH*NH), 256>>>(qp, kp, attn);

    // fused softmax (writes final probs) + AV + head merge
    fsav_kernel<<<dim3(SEQ/16, BATCH*NH), 256, S_FSAV>>>(attn, vt, vals);

    // o = vals @ Wo^T + bo + plm (residual fused)
    gemm_tf32<1,128,128,2,4><<<dim3(PLMD/128, ROWS/128, 1), 256, S_128_128>>>(
        vals, Wo, bo, plm, x, EMB, EMB, EMB, PLMD, 0,0,0, 1.f);

    // LayerNorm
    layernorm_kernel<<<ROWS, 256>>>(x, lng, lnb, ln);

    // FFN: gelu(ln @ Wd^T + bd)
    gemm_tf32<2,128,128,2,4><<<dim3(FFD/128, ROWS/128, 1), 256, S_128_128>>>(
        ln, Wd, bd, nullptr, ff, PLMD, PLMD, PLMD, FFD, 0,0,0, 1.f);

    // out = ff @ Wu^T + bu + ln (residual fused) -> d_out
    gemm_tf32<1,128,128,2,4><<<dim3(PLMD/128, ROWS/128, 1), 256, S_128_128>>>(
        ff, Wu, bu, ln, out, FFD, FFD, FFD, PLMD, 0,0,0, 1.f);
}

// round 5
// speedup vs baseline: 1.3509x; 1.3509x over previous
#include <cuda_runtime.h>
#include <math.h>
#include <stdint.h>

#define BATCH 2
#define SEQ   2048
#define NH    12
#define HD    64
#define EMB   768     // NH*HD
#define PLMD  1280
#define SD    128
#define FFD   640
#define ROWS  (BATCH*SEQ)                 // 4096
#define BH    (BATCH*NH)                  // 24
#define OUT_ELEMS ((long)ROWS*PLMD)       // 5,242,880
#define LOG2_10000 13.287712379549449f

// ---------------- scratch (static __device__, no allocation) ----------------
__device__ __align__(16) float g_qp[ROWS*EMB];
__device__ __align__(16) float g_kp[ROWS*EMB];
__device__ __align__(16) float g_vp[ROWS*EMB];
__device__ __align__(16) float g_vt[ROWS*EMB];   // [B,H,D,S]
__device__ __align__(16) float g_vals[ROWS*EMB]; // [B,S,E]
__device__ __align__(16) float g_x[ROWS*PLMD];
__device__ __align__(16) float g_ln[ROWS*PLMD];
__device__ __align__(16) float g_ff[ROWS*FFD];
__device__ __align__(16) float g_cos[SEQ*32];
__device__ __align__(16) float g_sin[SEQ*32];
__device__ __align__(16) float g_pmax[BH*16*SEQ];  // [bh][colblk][row]
__device__ __align__(16) float g_psum[BH*16*SEQ];
__device__ __align__(16) float g_rmax[BH*SEQ];
__device__ __align__(16) float g_rinv[BH*SEQ];

// ---------------- helpers ----------------
__device__ __forceinline__ uint32_t f2tf32(uint32_t xbits) {
    uint32_t u;
    float f = __uint_as_float(xbits);
    asm("cvt.rna.tf32.f32 %0, %1;" : "=r"(u) : "f"(f));
    return u;
}
__device__ __forceinline__ uint32_t f2tf32f(float f) {
    uint32_t u;
    asm("cvt.rna.tf32.f32 %0, %1;" : "=r"(u) : "f"(f));
    return u;
}

__device__ __forceinline__ void mma_tf32(float* c, const uint32_t* a, const uint32_t* b) {
    asm volatile("mma.sync.aligned.m16n8k8.row.col.f32.tf32.tf32.f32 "
        "{%0,%1,%2,%3}, {%4,%5,%6,%7}, {%8,%9}, {%0,%1,%2,%3};"
        : "+f"(c[0]), "+f"(c[1]), "+f"(c[2]), "+f"(c[3])
        : "r"(a[0]), "r"(a[1]), "r"(a[2]), "r"(a[3]), "r"(b[0]), "r"(b[1]));
}

__device__ __forceinline__ void cp_async16(uint32_t smem_dst, const void* gsrc) {
    asm volatile("cp.async.cg.shared.global [%0], [%1], 16;" :: "r"(smem_dst), "l"(gsrc));
}
__device__ __forceinline__ void cp_commit() { asm volatile("cp.async.commit_group;"); }
__device__ __forceinline__ void cp_wait1()  { asm volatile("cp.async.wait_group 1;"); }

// ---------------- RoPE cos/sin tables ----------------
__global__ void rope_table_kernel() {
    int idx = blockIdx.x * blockDim.x + threadIdx.x;
    if (idx >= SEQ*32) return;
    int s = idx >> 5, j = idx & 31;
    float inv = exp2f(-(float)j * (LOG2_10000 / 32.0f));
    float freq = (float)s * inv;
    float sn, c;
    sincosf(freq, &sn, &c);
    g_cos[idx] = c; g_sin[idx] = sn;
}

// ---------------- TF32 pipelined GEMM: C = alpha*A@B^T (+bias)(+extra)(gelu) ----
// EPI: 0 = (+bias), 1 = +bias+extra, 2 = gelu(+bias)
template<int EPI, int BM, int BN, int WARPS_M, int WARPS_N>
__global__ __launch_bounds__(256)
void gemm_tf32(const float* __restrict__ A, const float* __restrict__ B,
               const float* __restrict__ bias, const float* __restrict__ extra,
               float* __restrict__ C,
               int K, int sAm, int sBn, int ldc, float alpha)
{
    constexpr int BK   = 32;
    constexpr int LDSW = 36;
    constexpr int WM = BM / WARPS_M, WN = BN / WARPS_N;
    constexpr int MF = WM / 16, NF = WN / 8;
    constexpr int ASTG = BM * LDSW;
    constexpr int BSTG = BN * LDSW;

    extern __shared__ uint32_t smem[];
    uint32_t* As = smem;
    uint32_t* Bs = smem + 2 * ASTG;

    const int tid  = threadIdx.x;
    const int lane = tid & 31;
    const int warp = tid >> 5;
    const int wm = warp % WARPS_M, wn = warp / WARPS_M;
    const int row0 = blockIdx.y * BM, col0 = blockIdx.x * BN;
    A += (long)row0 * sAm;
    B += (long)col0 * sBn;

    const uint32_t smem_base = (uint32_t)__cvta_generic_to_shared(smem);

    const int r  = lane >> 2;
    const int cq = lane & 3;

    float acc[MF][NF][4];
#pragma unroll
    for (int m = 0; m < MF; m++)
#pragma unroll
        for (int n = 0; n < NF; n++)
#pragma unroll
            for (int j = 0; j < 4; j++) acc[m][n][j] = 0.f;

    const int lrow = tid >> 3;
    const int lf   = (tid & 7) * 4;

    auto prefetch = [&](int stage, int k0) {
#pragma unroll
        for (int i = 0; i < BM/32; i++) {
            int row = lrow + i*32;
            cp_async16(smem_base + (stage*ASTG + row*LDSW + lf)*4,
                       A + (long)row*sAm + k0 + lf);
        }
#pragma unroll
        for (int i = 0; i < BN/32; i++) {
            int row = lrow + i*32;
            cp_async16(smem_base + ((2*ASTG) + stage*BSTG + row*LDSW + lf)*4,
                       B + (long)row*sBn + k0 + lf);
        }
    };

    const int nk = K / BK;
    prefetch(0, 0);
    cp_commit();

    for (int kt = 0; kt < nk; kt++) {
        const int stage = kt & 1;
        if (kt + 1 < nk) prefetch(stage ^ 1, (kt+1) * BK);
        cp_commit();
        cp_wait1();
        __syncthreads();

        const uint32_t* Ast = As + stage * ASTG;
        const uint32_t* Bst = Bs + stage * BSTG;
#pragma unroll
        for (int ks = 0; ks < BK/8; ks++) {
            const int kk = ks * 8;
            uint32_t af[MF][4], bf[NF][2];
#pragma unroll
            for (int m = 0; m < MF; m++) {
                int base = (wm*WM + m*16 + r)*LDSW + kk + cq;
                af[m][0] = f2tf32(Ast[base]);
                af[m][1] = f2tf32(Ast[base + 8*LDSW]);
                af[m][2] = f2tf32(Ast[base + 4]);
                af[m][3] = f2tf32(Ast[base + 8*LDSW + 4]);
            }
#pragma unroll
            for (int n = 0; n < NF; n++) {
                int base = (wn*WN + n*8 + r)*LDSW + kk + cq;
                bf[n][0] = f2tf32(Bst[base]);
                bf[n][1] = f2tf32(Bst[base + 4]);
            }
#pragma unroll
            for (int m = 0; m < MF; m++)
#pragma unroll
                for (int n = 0; n < NF; n++)
                    mma_tf32(acc[m][n], af[m], bf[n]);
        }
        __syncthreads();
    }

#pragma unroll
    for (int m = 0; m < MF; m++) {
#pragma unroll
        for (int n = 0; n < NF; n++) {
            int row = row0 + wm*WM + m*16 + r;
            int col = col0 + wn*WN + n*8 + 2*cq;
            float v0 = alpha * acc[m][n][0];
            float v1 = alpha * acc[m][n][1];
            float v2 = alpha * acc[m][n][2];
            float v3 = alpha * acc[m][n][3];
            if (bias) { v0 += bias[col]; v1 += bias[col+1]; v2 += bias[col]; v3 += bias[col+1]; }
            if (EPI == 1) {
                v0 += extra[(long)row*ldc + col];
                v1 += extra[(long)row*ldc + col + 1];
                v2 += extra[(long)(row+8)*ldc + col];
                v3 += extra[(long)(row+8)*ldc + col + 1];
            }
            if (EPI == 2) {
                v0 = 0.5f * v0 * (1.f + erff(v0 * 0.70710678118654752f));
                v1 = 0.5f * v1 * (1.f + erff(v1 * 0.70710678118654752f));
                v2 = 0.5f * v2 * (1.f + erff(v2 * 0.70710678118654752f));
                v3 = 0.5f * v3 * (1.f + erff(v3 * 0.70710678118654752f));
            }
            *reinterpret_cast<float2*>(&C[(long)row*ldc + col])     = make_float2(v0, v1);
            *reinterpret_cast<float2*>(&C[(long)(row+8)*ldc + col]) = make_float2(v2, v3);
        }
    }
}

// ---------------- QK^T with fused RoPE + per-block softmax partial stats ----
// Writes scaled logits to attn [BH,S,S]; partial row max / sum-exp to g_pmax/g_psum.
__global__ __launch_bounds__(256)
void qk_rope_stats_kernel(const float* __restrict__ qp, const float* __restrict__ kp,
                          float* __restrict__ attn)
{
    constexpr int LDSW = 68;
    extern __shared__ float sm[];
    float* Qs = sm;                 // [128*LDSW]
    float* Ks = sm + 128*LDSW;

    const int tid  = threadIdx.x;
    const int lane = tid & 31;
    const int warp = tid >> 5;
    const int wm = warp & 1, wn = warp >> 1;   // 2 x 4 warps
    const int bh = blockIdx.z;
    const int b = bh / NH, h = bh % NH;
    const int row0 = blockIdx.y * 128, col0 = blockIdx.x * 128;

    const float* qb = qp + (long)b*SEQ*EMB + h*HD;
    const float* kb = kp + (long)b*SEQ*EMB + h*HD;

#pragma unroll
    for (int i = 0; i < 8; i++) {
        int idx = tid + i*256;
        int rr = idx >> 4, f = idx & 15;
        int d0 = f*4;
        int j0 = d0 & 31;
        float sgn = (d0 < 32) ? -1.f : 1.f;
        {   // Q
            int s = row0 + rr;
            float4 x  = *reinterpret_cast<const float4*>(qb + (long)s*EMB + d0);
            float4 p  = *reinterpret_cast<const float4*>(qb + (long)s*EMB + (d0 ^ 32));
            float4 c  = *reinterpret_cast<const float4*>(&g_cos[s*32 + j0]);
            float4 sn = *reinterpret_cast<const float4*>(&g_sin[s*32 + j0]);
            float4 o;
            o.x = x.x*c.x + sgn*p.x*sn.x;
            o.y = x.y*c.y + sgn*p.y*sn.y;
            o.z = x.z*c.z + sgn*p.z*sn.z;
            o.w = x.w*c.w + sgn*p.w*sn.w;
            *reinterpret_cast<float4*>(&Qs[rr*LDSW + d0]) = o;
        }
        {   // K
            int s = col0 + rr;
            float4 x  = *reinterpret_cast<const float4*>(kb + (long)s*EMB + d0);
            float4 p  = *reinterpret_cast<const float4*>(kb + (long)s*EMB + (d0 ^ 32));
            float4 c  = *reinterpret_cast<const float4*>(&g_cos[s*32 + j0]);
            float4 sn = *reinterpret_cast<const float4*>(&g_sin[s*32 + j0]);
            float4 o;
            o.x = x.x*c.x + sgn*p.x*sn.x;
            o.y = x.y*c.y + sgn*p.y*sn.y;
            o.z = x.z*c.z + sgn*p.z*sn.z;
            o.w = x.w*c.w + sgn*p.w*sn.w;
            *reinterpret_cast<float4*>(&Ks[rr*LDSW + d0]) = o;
        }
    }
    __syncthreads();

    const int r  = lane >> 2;
    const int cq = lane & 3;
    float acc[4][4][4];
#pragma unroll
    for (int m = 0; m < 4; m++)
#pragma unroll
        for (int n = 0; n < 4; n++)
#pragma unroll
            for (int j = 0; j < 4; j++) acc[m][n][j] = 0.f;

#pragma unroll
    for (int ks = 0; ks < 8; ks++) {
        const int kk = ks * 8;
        uint32_t af[4][4], bf[4][2];
#pragma unroll
        for (int m = 0; m < 4; m++) {
            int base = (wm*64 + m*16 + r)*LDSW + kk + cq;
            af[m][0] = f2tf32f(Qs[base]);
            af[m][1] = f2tf32f(Qs[base + 8*LDSW]);
            af[m][2] = f2tf32f(Qs[base + 4]);
            af[m][3] = f2tf32f(Qs[base + 8*LDSW + 4]);
        }
#pragma unroll
        for (int n = 0; n < 4; n++) {
            int base = (wn*32 + n*8 + r)*LDSW + kk + cq;
            bf[n][0] = f2tf32f(Ks[base]);
            bf[n][1] = f2tf32f(Ks[base + 4]);
        }
#pragma unroll
        for (int m = 0; m < 4; m++)
#pragma unroll
            for (int n = 0; n < 4; n++)
                mma_tf32(acc[m][n], af[m], bf[n]);
    }

    // scale + write logits
#pragma unroll
    for (int m = 0; m < 4; m++)
#pragma unroll
        for (int n = 0; n < 4; n++)
#pragma unroll
            for (int j = 0; j < 4; j++) acc[m][n][j] *= 0.125f;

    float* Cb = attn + (long)bh*SEQ*SEQ;
#pragma unroll
    for (int m = 0; m < 4; m++) {
#pragma unroll
        for (int n = 0; n < 4; n++) {
            int row = row0 + wm*64 + m*16 + r;
            int col = col0 + wn*32 + n*8 + 2*cq;
            *reinterpret_cast<float2*>(&Cb[(long)row*SEQ + col]) =
                make_float2(acc[m][n][0], acc[m][n][1]);
            *reinterpret_cast<float2*>(&Cb[(long)(row+8)*SEQ + col]) =
                make_float2(acc[m][n][2], acc[m][n][3]);
        }
    }

    // ---- partial softmax stats over this block's 128 cols ----
    __syncthreads();              // done with Qs/Ks; reuse as reduction array
    float* Sred = sm;             // [128][17]
    const int slot = wn*4 + cq;

#pragma unroll
    for (int m = 0; m < 4; m++)
#pragma unroll
        for (int hf = 0; hf < 2; hf++) {
            int rl = wm*64 + m*16 + r + hf*8;
            float mx = -1e30f;
#pragma unroll
            for (int n = 0; n < 4; n++)
                mx = fmaxf(mx, fmaxf(acc[m][n][hf*2], acc[m][n][hf*2+1]));
            Sred[rl*17 + slot] = mx;
        }
    __syncthreads();
    if (tid < 128) {
        float mx = -1e30f;
#pragma unroll
        for (int i = 0; i < 16; i++) mx = fmaxf(mx, Sred[tid*17 + i]);
        Sred[tid*17 + 16] = mx;
    }
    __syncthreads();
#pragma unroll
    for (int m = 0; m < 4; m++)
#pragma unroll
        for (int hf = 0; hf < 2; hf++) {
            int rl = wm*64 + m*16 + r + hf*8;
            float mx = Sred[rl*17 + 16];
            float s = 0.f;
#pragma unroll
            for (int n = 0; n < 4; n++)
                s += __expf(acc[m][n][hf*2] - mx) + __expf(acc[m][n][hf*2+1] - mx);
            Sred[rl*17 + slot] = s;
        }
    __syncthreads();
    if (tid < 128) {
        float s = 0.f;
#pragma unroll
        for (int i = 0; i < 16; i++) s += Sred[tid*17 + i];
        long off = (long)(bh*16 + blockIdx.x)*SEQ + row0 + tid;
        g_pmax[off] = Sred[tid*17 + 16];
        g_psum[off] = s;
    }
}

// ---------------- reduce 16 partials per row -> row max + 1/sum ----------------
__global__ __launch_bounds__(256)
void reduce_stats_kernel()
{
    int rg = blockIdx.x * 256 + threadIdx.x;   // 0..BH*SEQ-1
    if (rg >= BH*SEQ) return;
    int bh = rg >> 11, row = rg & (SEQ-1);
    long base = (long)bh*16*SEQ + row;
    float m = -1e30f;
#pragma unroll
    for (int i = 0; i < 16; i++) m = fmaxf(m, g_pmax[base + (long)i*SEQ]);
    float s = 0.f;
#pragma unroll
    for (int i = 0; i < 16; i++)
        s += g_psum[base + (long)i*SEQ] * __expf(g_pmax[base + (long)i*SEQ] - m);
    g_rmax[rg] = m;
    g_rinv[rg] = 1.f / s;
}

// ---------------- AV with in-SMEM normalization; writes probs + merged O ------
// A = logits tile (normalized in SMEM -> streamed to d_out as final probs),
// B = V^T [B,H,D,S]. O written directly in [B,S,H*D]. BM=128, BN=64, BK=32.
__global__ __launch_bounds__(256)
void av_norm_kernel(float* __restrict__ attn, const float* __restrict__ vt,
                    float* __restrict__ vals)
{
    constexpr int BM = 128, BN = 64, BK = 32, LDSW = 36;
    constexpr int WARPS_M = 4, WARPS_N = 2;
    constexpr int WM = BM/WARPS_M, WN = BN/WARPS_N;   // 32, 32
    constexpr int MF = WM/16, NF = WN/8;              // 2, 4
    constexpr int ASTG = BM*LDSW, BSTG = BN*LDSW;

    extern __shared__ float smf[];
    float* As = smf;
    float* Bs = smf + 2*ASTG;

    const int tid  = threadIdx.x;
    const int lane = tid & 31;
    const int warp = tid >> 5;
    const int wm = warp % WARPS_M, wn = warp / WARPS_M;
    const int bh = blockIdx.z;
    const int b = bh / NH, h = bh % NH;
    const int row0 = blockIdx.y * BM;

    float* Ab = attn + (long)bh*SEQ*SEQ + (long)row0*SEQ;
    const float* Bb = vt + (long)bh*HD*SEQ;

    const uint32_t smem_base = (uint32_t)__cvta_generic_to_shared(smf);

    const int r  = lane >> 2;
    const int cq = lane & 3;
    const int lrow = tid >> 3;
    const int lf   = (tid & 7) * 4;

    // row stats for the 4 rows this thread normalizes
    float rm[4], ri[4];
#pragma unroll
    for (int i = 0; i < 4; i++) {
        int rg = bh*SEQ + row0 + lrow + i*32;
        rm[i] = g_rmax[rg];
        ri[i] = g_rinv[rg];
    }

    float acc[MF][NF][4];
#pragma unroll
    for (int m = 0; m < MF; m++)
#pragma unroll
        for (int n = 0; n < NF; n++)
#pragma unroll
            for (int j = 0; j < 4; j++) acc[m][n][j] = 0.f;

    auto prefetch = [&](int stage, int k0) {
#pragma unroll
        for (int i = 0; i < BM/32; i++) {
            int row = lrow + i*32;
            cp_async16(smem_base + (stage*ASTG + row*LDSW + lf)*4,
                       Ab + (long)row*SEQ + k0 + lf);
        }
#pragma unroll
        for (int i = 0; i < BN/32; i++) {
            int row = lrow + i*32;
            cp_async16(smem_base + ((2*ASTG) + stage*BSTG + row*LDSW + lf)*4,
                       Bb + (long)row*SEQ + k0 + lf);
        }
    };

    const int nk = SEQ / BK;     // 64
    prefetch(0, 0);
    cp_commit();

    for (int kt = 0; kt < nk; kt++) {
        const int stage = kt & 1;
        if (kt + 1 < nk) prefetch(stage ^ 1, (kt+1) * BK);
        cp_commit();
        cp_wait1();
        __syncthreads();

        // normalize staged logits -> probs (SMEM) and stream to d_out
#pragma unroll
        for (int i = 0; i < 4; i++) {
            int row = lrow + i*32;
            float* p = &As[stage*ASTG + row*LDSW + lf];
            float4 v = *reinterpret_cast<float4*>(p);
            v.x = __expf(v.x - rm[i]) * ri[i];
            v.y = __expf(v.y - rm[i]) * ri[i];
            v.z = __expf(v.z - rm[i]) * ri[i];
            v.w = __expf(v.w - rm[i]) * ri[i];
            *reinterpret_cast<float4*>(p) = v;
            __stcs(reinterpret_cast<float4*>(Ab + (long)row*SEQ + kt*BK + lf), v);
        }
        __syncthreads();

        const float* Ast = As + stage*ASTG;
        const float* Bst = Bs + stage*BSTG;
#pragma unroll
        for (int ks = 0; ks < BK/8; ks++) {
            const int kk = ks * 8;
            uint32_t af[MF][4], bf[NF][2];
#pragma unroll
            for (int m = 0; m < MF; m++) {
                int base = (wm*WM + m*16 + r)*LDSW + kk + cq;
                af[m][0] = f2tf32f(Ast[base]);
                af[m][1] = f2tf32f(Ast[base + 8*LDSW]);
                af[m][2] = f2tf32f(Ast[base + 4]);
                af[m][3] = f2tf32f(Ast[base + 8*LDSW + 4]);
            }
#pragma unroll
            for (int n = 0; n < NF; n++) {
                int base = (wn*WN + n*8 + r)*LDSW + kk + cq;
                bf[n][0] = f2tf32f(Bst[base]);
                bf[n][1] = f2tf32f(Bst[base + 4]);
            }
#pragma unroll
            for (int m = 0; m < MF; m++)
#pragma unroll
                for (int n = 0; n < NF; n++)
                    mma_tf32(acc[m][n], af[m], bf[n]);
        }
        __syncthreads();
    }

    // epilogue: write O in merged [B,S,H*D] layout
#pragma unroll
    for (int m = 0; m < MF; m++) {
#pragma unroll
        for (int n = 0; n < NF; n++) {
            int srow = row0 + wm*WM + m*16 + r;
            int col  = h*HD + wn*WN + n*8 + 2*cq;
            *reinterpret_cast<float2*>(&vals[(long)(b*SEQ + srow)*EMB + col]) =
                make_float2(acc[m][n][0], acc[m][n][1]);
            *reinterpret_cast<float2*>(&vals[(long)(b*SEQ + srow + 8)*EMB + col]) =
                make_float2(acc[m][n][2], acc[m][n][3]);
        }
    }
}

// ---------------- V transpose: [B,S,H*D] -> [B,H,D,S] ----------------
__global__ void v_transpose_kernel(const float* __restrict__ src, float* __restrict__ dst)
{
    int idx = blockIdx.x * blockDim.x + threadIdx.x;
    if (idx >= ROWS*EMB) return;
    int d = idx & 63;
    int s = (idx >> 6) & (SEQ-1);
    int t = idx >> 17;
    int h = t % NH;
    int b = t / NH;
    float val = src[(long)(b*SEQ + s)*EMB + h*HD + d];
    dst[((long)(b*NH + h)*HD + d)*SEQ + s] = val;
}

// ---------------- LayerNorm over 1280 ----------------
__global__ __launch_bounds__(256) void layernorm_kernel(const float* __restrict__ x,
    const float* __restrict__ g, const float* __restrict__ b, float* __restrict__ y)
{
    __shared__ float buf[PLMD];
    __shared__ float red[256];
    long row = blockIdx.x;
    const float* xr = x + row*PLMD;
    int tid = threadIdx.x;
    float s = 0.f;
    for (int i = tid; i < PLMD; i += 256) { float t = xr[i]; buf[i] = t; s += t; }
    red[tid] = s; __syncthreads();
    for (int st = 128; st > 0; st >>= 1) { if (tid < st) red[tid] += red[tid+st]; __syncthreads(); }
    float mu = red[0] * (1.f/PLMD); __syncthreads();
    float vs = 0.f;
    for (int i = tid; i < PLMD; i += 256) { float d = buf[i] - mu; vs += d*d; }
    red[tid] = vs; __syncthreads();
    for (int st = 128; st > 0; st >>= 1) { if (tid < st) red[tid] += red[tid+st]; __syncthreads(); }
    float rstd = rsqrtf(red[0] * (1.f/PLMD) + 1e-5f);
    float* yr = y + row*PLMD;
    for (int i = tid; i < PLMD; i += 256) yr[i] = (buf[i] - mu) * rstd * g[i] + b[i];
}

// ---------------- launch ----------------
extern "C" void kernel_launch(void* const* d_in, const int* in_sizes, int n_in,
                              void* d_out, int out_size)
{
    const float* s_repre = (const float*)d_in[0];
    const float* plm     = (const float*)d_in[1];
    const float* Wq = (const float*)d_in[2];  const float* bq = (const float*)d_in[3];
    const float* Wk = (const float*)d_in[4];  const float* bk = (const float*)d_in[5];
    const float* Wv = (const float*)d_in[6];  const float* bv = (const float*)d_in[7];
    const float* Wo = (const float*)d_in[8];  const float* bo = (const float*)d_in[9];
    const float* lng = (const float*)d_in[10]; const float* lnb = (const float*)d_in[11];
    const float* Wd = (const float*)d_in[12]; const float* bd = (const float*)d_in[13];
    const float* Wu = (const float*)d_in[14]; const float* bu = (const float*)d_in[15];

    float* out  = (float*)d_out;
    float* attn = out + OUT_ELEMS;   // tuple order: (out, attention)

    float *qp,*kp,*vp,*vt,*vals,*x,*ln,*ff;
    cudaGetSymbolAddress((void**)&qp, g_qp);
    cudaGetSymbolAddress((void**)&kp, g_kp);
    cudaGetSymbolAddress((void**)&vp, g_vp);
    cudaGetSymbolAddress((void**)&vt, g_vt);
    cudaGetSymbolAddress((void**)&vals, g_vals);
    cudaGetSymbolAddress((void**)&x, g_x);
    cudaGetSymbolAddress((void**)&ln, g_ln);
    cudaGetSymbolAddress((void**)&ff, g_ff);

    const int S_128_128 = 2 * (128 + 128) * 36 * 4;   // 73728
    const int S_QK   = 2 * 128 * 68 * 4;              // 69632
    const int S_AV   = 2 * (128 + 64) * 36 * 4;       // 55296
    cudaFuncSetAttribute(gemm_tf32<0,128,128,2,4>, cudaFuncAttributeMaxDynamicSharedMemorySize, S_128_128);
    cudaFuncSetAttribute(gemm_tf32<1,128,128,2,4>, cudaFuncAttributeMaxDynamicSharedMemorySize, S_128_128);
    cudaFuncSetAttribute(gemm_tf32<2,128,128,2,4>, cudaFuncAttributeMaxDynamicSharedMemorySize, S_128_128);
    cudaFuncSetAttribute(qk_rope_stats_kernel, cudaFuncAttributeMaxDynamicSharedMemorySize, S_QK);
    cudaFuncSetAttribute(av_norm_kernel, cudaFuncAttributeMaxDynamicSharedMemorySize, S_AV);

    const int tot = ROWS*EMB;

    // RoPE tables
    rope_table_kernel<<<(SEQ*32 + 255)/256, 256>>>();

    // QKV projections
    gemm_tf32<0,128,128,2,4><<<dim3(EMB/128, ROWS/128, 1), 256, S_128_128>>>(
        plm, Wq, bq, nullptr, qp, PLMD, PLMD, PLMD, EMB, 1.f);
    gemm_tf32<0,128,128,2,4><<<dim3(EMB/128, ROWS/128, 1), 256, S_128_128>>>(
        s_repre, Wk, bk, nullptr, kp, SD, SD, SD, EMB, 1.f);
    gemm_tf32<0,128,128,2,4><<<dim3(EMB/128, ROWS/128, 1), 256, S_128_128>>>(
        s_repre, Wv, bv, nullptr, vp, SD, SD, SD, EMB, 1.f);

    // V transpose to [B,H,D,S]
    v_transpose_kernel<<<(tot+255)/256, 256>>>(vp, vt);

    // logits = RoPE(q) @ RoPE(k)^T / 8 -> attn region, + partial softmax stats
    qk_rope_stats_kernel<<<dim3(SEQ/128, SEQ/128, BH), 256, S_QK>>>(qp, kp, attn);

    // finalize row stats
    reduce_stats_kernel<<<(BH*SEQ + 255)/256, 256>>>();

    // AV: normalize logits -> probs (written to d_out) + P@V -> merged vals
    av_norm_kernel<<<dim3(1, SEQ/128, BH), 256, S_AV>>>(attn, vt, vals);

    // o = vals @ Wo^T + bo + plm (residual fused)
    gemm_tf32<1,128,128,2,4><<<dim3(PLMD/128, ROWS/128, 1), 256, S_128_128>>>(
        vals, Wo, bo, plm, x, EMB, EMB, EMB, PLMD, 1.f);

    // LayerNorm
    layernorm_kernel<<<ROWS, 256>>>(x, lng, lnb, ln);

    // FFN: gelu(ln @ Wd^T + bd)
    gemm_tf32<2,128,128,2,4><<<dim3(FFD/128, ROWS/128, 1), 256, S_128_128>>>(
        ln, Wd, bd, nullptr, ff, PLMD, PLMD, PLMD, FFD, 1.f);

    // out = ff @ Wu^T + bu + ln (residual fused) -> d_out
    gemm_tf32<1,128,128,2,4><<<dim3(PLMD/128, ROWS/128, 1), 256, S_128_128>>>(
        ff, Wu, bu, ln, out, FFD, FFD, FFD, PLMD, 1.f);
}